// round 2
// baseline (speedup 1.0000x reference)
#include <cuda_runtime.h>
#include <cuda_bf16.h>

#define NN 100000
#define EE 3200000
#define HD 64
#define BN_EPS 1e-5f

// ---------------- scratch (device globals; no allocation allowed) ----------------
__device__ float g_deg[NN];
__device__ int   g_src[EE];
__device__ int   g_dst[EE];
__device__ float g_coef[EE];
__device__ __align__(16) float g_buf1[NN * HD];
__device__ __align__(16) float g_buf2[NN * HD];
__device__ float g_stats[6 * HD];      // sum1,sq1 | sum2,sq2 | sum3,sq3
__device__ float g_W2f[HD * HD];
__device__ float g_cb2[HD];
__device__ float g_W3f[HD * HD];
__device__ float g_d3[HD];
__device__ __align__(16) float g_wfbf[HD + 4];   // folded final weights + scalar bias

// ---------------- kernels ----------------

__global__ void init_k(float* deg, float* stats, int n) {
    int i = blockIdx.x * blockDim.x + threadIdx.x;
    if (i < n) deg[i] = 1.0f;                 // self-loop weight
    if (i < 6 * HD) stats[i] = 0.0f;
}

// edge_index is int32 (JAX x64 disabled downcasts the requested int64)
__global__ void deg_k(const int* __restrict__ ei, const float* __restrict__ ew,
                      float* deg, int* srcb, int* dstb) {
    int e = blockIdx.x * blockDim.x + threadIdx.x;
    if (e >= EE) return;
    int s = ei[e];
    int d = ei[EE + e];
    srcb[e] = s;
    dstb[e] = d;
    atomicAdd(&deg[d], ew[e]);
}

__global__ void coef_k(const float* __restrict__ ew, const float* __restrict__ deg,
                       const int* __restrict__ srcb, const int* __restrict__ dstb,
                       float* coef) {
    int e = blockIdx.x * blockDim.x + threadIdx.x;
    if (e >= EE) return;
    coef[e] = ew[e] * rsqrtf(deg[srcb[e]]) * rsqrtf(deg[dstb[e]]);
}

// C[n,64] = A[n,K] @ W[K,64] (+ optional bias). TILE_M=64, 256 threads.
template <int K>
__global__ void gemm_k(const float* __restrict__ A, const float* __restrict__ W,
                       const float* __restrict__ bias, float* __restrict__ C, int n) {
    constexpr int TM = 64;
    constexpr int KC = 64;
    __shared__ float As[KC][TM + 4];
    __shared__ float Ws[KC][64];
    const int tid = threadIdx.x;
    const int tx = tid & 15;          // col group: cols tx*4..tx*4+3
    const int ty = tid >> 4;          // row group: rows ty*4..ty*4+3
    const int m_base = blockIdx.x * TM;

    float acc[4][4] = {};

    for (int kk = 0; kk < K; kk += KC) {
        for (int idx = tid; idx < TM * KC; idx += 256) {
            int m = idx / KC, k = idx % KC;
            int row = m_base + m;
            As[k][m] = (row < n) ? A[row * K + kk + k] : 0.0f;
        }
        for (int idx = tid; idx < KC * 64; idx += 256) {
            int k = idx >> 6, c = idx & 63;
            Ws[k][c] = W[(kk + k) * 64 + c];
        }
        __syncthreads();
#pragma unroll 16
        for (int k = 0; k < KC; k++) {
            float4 a = *(const float4*)&As[k][ty * 4];
            float4 b = *(const float4*)&Ws[k][tx * 4];
            float av[4] = {a.x, a.y, a.z, a.w};
            float bv[4] = {b.x, b.y, b.z, b.w};
#pragma unroll
            for (int i = 0; i < 4; i++)
#pragma unroll
                for (int j = 0; j < 4; j++)
                    acc[i][j] += av[i] * bv[j];
        }
        __syncthreads();
    }

#pragma unroll
    for (int i = 0; i < 4; i++) {
        int row = m_base + ty * 4 + i;
        if (row >= n) break;
#pragma unroll
        for (int j = 0; j < 4; j++) {
            int col = tx * 4 + j;
            float v = acc[i][j];
            if (bias) v += bias[col];
            C[row * 64 + col] = v;
        }
    }
}

// out[i] = h[i] / deg[i]  (self-loop contribution: dis[i]^2 == 1/deg[i])
__global__ void initagg_k(const float4* __restrict__ in, const float* __restrict__ deg,
                          float4* __restrict__ out, int n) {
    int i = blockIdx.x * blockDim.x + threadIdx.x;
    if (i >= n * 16) return;
    float s = __fdividef(1.0f, deg[i >> 4]);
    float4 v = in[i];
    v.x *= s; v.y *= s; v.z *= s; v.w *= s;
    out[i] = v;
}

// 16 threads per edge; each thread handles one float4 of the 64-float row.
__global__ void scatter_k(const float4* __restrict__ in,
                          const int* __restrict__ srcb, const int* __restrict__ dstb,
                          const float* __restrict__ coef, float4* __restrict__ out) {
    int t = blockIdx.x * blockDim.x + threadIdx.x;
    int e = t >> 4;
    if (e >= EE) return;
    int c = t & 15;
    float cf = coef[e];
    int s = srcb[e];
    int d = dstb[e];
    float4 v = in[s * 16 + c];
    float4* p = out + (d * 16 + c);
    asm volatile("red.global.add.v4.f32 [%0], {%1, %2, %3, %4};" ::
                 "l"(p), "f"(v.x * cf), "f"(v.y * cf), "f"(v.z * cf), "f"(v.w * cf)
                 : "memory");
}

// Per-feature sum & sum-of-squares. mode=1: v = relu(v + bias[f]) written back first.
__global__ void stats_k(float* __restrict__ buf, const float* __restrict__ bias,
                        float* __restrict__ stats, int mode, int n) {
    __shared__ float ssum[8][64];
    __shared__ float ssq[8][64];
    int f = threadIdx.x;
    int ty = threadIdx.y;
    float s = 0.0f, q = 0.0f;
    for (int row = blockIdx.x * 8 + ty; row < n; row += gridDim.x * 8) {
        float v = buf[row * 64 + f];
        if (mode) {
            v = fmaxf(v + bias[f], 0.0f);
            buf[row * 64 + f] = v;
        }
        s += v;
        q += v * v;
    }
    ssum[ty][f] = s;
    ssq[ty][f] = q;
    __syncthreads();
    if (ty == 0) {
#pragma unroll
        for (int i = 1; i < 8; i++) { s += ssum[i][f]; q += ssq[i][f]; }
        atomicAdd(&stats[f], s);
        atomicAdd(&stats[64 + f], q);
    }
}

// Fold BN (a = g*rsqrt(var+eps), c = beta - mean*a) into next 64x64 linear layer.
// add_bn=1: bf = bn + c@Wn (post-gemm bias, no aggregation after)
// add_bn=0: bf = c@Wn only (pre-aggregation constant; the GCN bias after
//           aggregation is per-feature constant and cancels in the next BN).
__global__ void fold_k(const float* __restrict__ stats, const float* __restrict__ g,
                       const float* __restrict__ beta, const float* __restrict__ Wn,
                       const float* __restrict__ bn, float* __restrict__ Wf,
                       float* __restrict__ bf, int add_bn) {
    __shared__ float a[64], c[64];
    int t = threadIdx.x;
    if (t < 64) {
        float mean = stats[t] * (1.0f / NN);
        float var = stats[64 + t] * (1.0f / NN) - mean * mean;
        float rs = rsqrtf(var + BN_EPS);
        a[t] = g[t] * rs;
        c[t] = beta[t] - mean * a[t];
    }
    __syncthreads();
    for (int idx = t; idx < 64 * 64; idx += blockDim.x)
        Wf[idx] = a[idx >> 6] * Wn[idx];
    if (t < 64) {
        float s = add_bn ? bn[t] : 0.0f;
#pragma unroll 8
        for (int k = 0; k < 64; k++) s += c[k] * Wn[k * 64 + t];
        bf[t] = s;
    }
}

// Fold BN3 + lin2 ([64,1]) into a single 64-vector + scalar.
__global__ void fold3_k(const float* __restrict__ stats, const float* __restrict__ g,
                        const float* __restrict__ beta, const float* __restrict__ w2,
                        const float* __restrict__ b2, float* __restrict__ wfbf) {
    __shared__ float cw[64];
    int t = threadIdx.x;   // 64 threads
    float mean = stats[t] * (1.0f / NN);
    float var = stats[64 + t] * (1.0f / NN) - mean * mean;
    float rs = rsqrtf(var + BN_EPS);
    float a = g[t] * rs;
    float c = beta[t] - mean * a;
    wfbf[t] = a * w2[t];
    cw[t] = c * w2[t];
    __syncthreads();
    if (t == 0) {
        float s = b2[0];
        for (int k = 0; k < 64; k++) s += cw[k];
        wfbf[64] = s;
    }
}

// One warp per node: out[i] = dot64(z[i], wf) + bf
__global__ void final_k(const float* __restrict__ z, const float* __restrict__ wfbf,
                        float* __restrict__ out, int n) {
    int warp = (blockIdx.x * blockDim.x + threadIdx.x) >> 5;
    int lane = threadIdx.x & 31;
    if (warp >= n) return;
    float2 v = ((const float2*)z)[warp * 32 + lane];
    float2 w = ((const float2*)wfbf)[lane];
    float s = v.x * w.x + v.y * w.y;
#pragma unroll
    for (int o = 16; o; o >>= 1) s += __shfl_down_sync(0xFFFFFFFFu, s, o);
    if (lane == 0) out[warp] = s + wfbf[64];
}

// ---------------- host launcher ----------------
extern "C" void kernel_launch(void* const* d_in, const int* in_sizes, int n_in,
                              void* d_out, int out_size) {
    const float* x       = (const float*)d_in[0];
    const float* ew      = (const float*)d_in[1];
    const float* W1      = (const float*)d_in[2];
    const float* b1      = (const float*)d_in[3];
    const float* W2      = (const float*)d_in[4];
    const float* lin1_W  = (const float*)d_in[6];
    const float* lin1_b  = (const float*)d_in[7];
    const float* lin2_W  = (const float*)d_in[8];
    const float* lin2_b  = (const float*)d_in[9];
    const float* bn1_g   = (const float*)d_in[10];
    const float* bn1_b   = (const float*)d_in[11];
    const float* bn2_g   = (const float*)d_in[12];
    const float* bn2_b   = (const float*)d_in[13];
    const float* bn3_g   = (const float*)d_in[14];
    const float* bn3_b   = (const float*)d_in[15];
    const int*   ei      = (const int*)d_in[16];     // int32 (JAX x64 disabled)
    float* out           = (float*)d_out;

    float *deg, *coef, *buf1, *buf2, *stats, *W2f, *cb2, *W3f, *d3, *wfbf;
    int *srcb, *dstb;
    cudaGetSymbolAddress((void**)&deg,   g_deg);
    cudaGetSymbolAddress((void**)&srcb,  g_src);
    cudaGetSymbolAddress((void**)&dstb,  g_dst);
    cudaGetSymbolAddress((void**)&coef,  g_coef);
    cudaGetSymbolAddress((void**)&buf1,  g_buf1);
    cudaGetSymbolAddress((void**)&buf2,  g_buf2);
    cudaGetSymbolAddress((void**)&stats, g_stats);
    cudaGetSymbolAddress((void**)&W2f,   g_W2f);
    cudaGetSymbolAddress((void**)&cb2,   g_cb2);
    cudaGetSymbolAddress((void**)&W3f,   g_W3f);
    cudaGetSymbolAddress((void**)&d3,    g_d3);
    cudaGetSymbolAddress((void**)&wfbf,  g_wfbf);

    const int TPB = 256;
    const int gInit  = (NN + TPB - 1) / TPB;
    const int gEdge  = (EE + TPB - 1) / TPB;
    const int gGemm  = (NN + 63) / 64;
    const int gElem  = (NN * 16 + TPB - 1) / TPB;
    const int gScat  = (EE * 16 + TPB - 1) / TPB;
    const dim3 statsBlk(64, 8);

    // graph prep shared by both GCN layers
    init_k<<<gInit, TPB>>>(deg, stats, NN);
    deg_k<<<gEdge, TPB>>>(ei, ew, deg, srcb, dstb);
    coef_k<<<gEdge, TPB>>>(ew, deg, srcb, dstb, coef);

    // layer 1: h = relu(agg(x@W1) + b1); bn1 folded into W2
    gemm_k<128><<<gGemm, TPB>>>(x, W1, nullptr, buf1, NN);
    initagg_k<<<gElem, TPB>>>((const float4*)buf1, deg, (float4*)buf2, NN);
    scatter_k<<<gScat, TPB>>>((const float4*)buf1, srcb, dstb, coef, (float4*)buf2);
    stats_k<<<512, statsBlk>>>(buf2, b1, stats + 0, 1, NN);
    fold_k<<<1, 256>>>(stats + 0, bn1_g, bn1_b, W2, nullptr, W2f, cb2, /*add_bn=*/0);

    // layer 2: agg(bn1(h)@W2); GCN bias b2 cancels in bn2. bn2 folded into lin1.
    gemm_k<64><<<gGemm, TPB>>>(buf2, W2f, cb2, buf1, NN);
    initagg_k<<<gElem, TPB>>>((const float4*)buf1, deg, (float4*)buf2, NN);
    scatter_k<<<gScat, TPB>>>((const float4*)buf1, srcb, dstb, coef, (float4*)buf2);
    stats_k<<<512, statsBlk>>>(buf2, nullptr, stats + 128, 0, NN);
    fold_k<<<1, 256>>>(stats + 128, bn2_g, bn2_b, lin1_W, lin1_b, W3f, d3, /*add_bn=*/1);

    // lin1 (+ folded bn2), then bn3 + lin2 folded into a single dot per node
    gemm_k<64><<<gGemm, TPB>>>(buf2, W3f, d3, buf1, NN);
    stats_k<<<512, statsBlk>>>(buf1, nullptr, stats + 256, 0, NN);
    fold3_k<<<1, 64>>>(stats + 256, bn3_g, bn3_b, lin2_W, lin2_b, wfbf);
    final_k<<<(NN * 32 + TPB - 1) / TPB, TPB>>>(buf1, wfbf, out, NN);
}